// round 14
// baseline (speedup 1.0000x reference)
#include <cuda_runtime.h>
#include <cuda_fp16.h>
#include <cstdint>

#define BATCH 8
#define DIM   512
#define LSEQ  8192

// ---------------- device scratch (static globals: allowed) ----------------
__device__ __half g_Wc[1024 * 512];                         //   1 MB
__device__ __half g_Xb[(size_t)65536 * 512];                //  64 MB [n=(b,l)][k]
__device__ __half2 g_AB[(size_t)BATCH * 512 * LSEQ];        // 128 MB  (a,b) pairs

__device__ __forceinline__ uint32_t smem_u32(const void* p) {
    uint32_t a;
    asm("{ .reg .u64 t; cvta.to.shared.u64 t, %1; cvt.u32.u64 %0, t; }"
        : "=r"(a) : "l"(p));
    return a;
}
__device__ __forceinline__ void ldsm4(uint32_t* d, uint32_t addr) {
    asm volatile("ldmatrix.sync.aligned.m8n8.x4.shared.b16 {%0,%1,%2,%3}, [%4];"
                 : "=r"(d[0]), "=r"(d[1]), "=r"(d[2]), "=r"(d[3]) : "r"(addr));
}
__device__ __forceinline__ void mma16816(float* c, const uint32_t* a,
                                         uint32_t b0, uint32_t b1) {
    asm volatile(
        "mma.sync.aligned.m16n8k16.row.col.f32.f16.f16.f32 "
        "{%0,%1,%2,%3}, {%4,%5,%6,%7}, {%8,%9}, {%0,%1,%2,%3};"
        : "+f"(c[0]), "+f"(c[1]), "+f"(c[2]), "+f"(c[3])
        : "r"(a[0]), "r"(a[1]), "r"(a[2]), "r"(a[3]), "r"(b0), "r"(b1));
}

// pointwise: a = sigmoid(-g), b = sigmoid(g) * (h>=0 ? 1+h : exp(h))
__device__ __forceinline__ void ab_elem(float h, float g, float& a, float& b) {
    float em = __expf(-g);
    float z  = __fdividef(1.f, 1.f + em);   // sigmoid(g); em=inf -> z=0
    a = 1.f - z;
    float gv = (h >= 0.f) ? (1.f + h) : __expf(h);
    b = z * gv;
}

// ---------------------------------------------------------------------------
// W converter: fragment-friendly row reorder, fp16 quantize.
// ---------------------------------------------------------------------------
__global__ __launch_bounds__(256)
void convert_w(const float* __restrict__ wf, const float* __restrict__ wb)
{
    int idx = blockIdx.x * 256 + threadIdx.x;        // 0..131071
    int r   = idx >> 7;                              // 0..1023
    int dq  = (idx & 127) * 4;                       // 0..508
    int g   = r >> 4, i = r & 15;
    int ch  = (g << 3) + (i & 7);                    // 0..511
    int gate = i >> 3;
    const float* src = (ch < 256)
        ? wf + (size_t)(gate * 256 + ch) * DIM + dq
        : wb + (size_t)(gate * 256 + ch - 256) * DIM + dq;
    float4 v = *reinterpret_cast<const float4*>(src);
    float vv[4] = {v.x, v.y, v.z, v.w};
#pragma unroll
    for (int j = 0; j < 4; j++)
        g_Wc[(size_t)r * 512 + dq + j] = __float2half(vv[j]);
}

// ---------------------------------------------------------------------------
// X converter: x[b][d][l] -> g_Xb[(b*8192+l)][d] fp16 via smem transpose.
// ---------------------------------------------------------------------------
__global__ __launch_bounds__(256)
void convert_x(const float* __restrict__ x)
{
    __shared__ float sm[32][65];
    const int b  = blockIdx.y;
    const int l0 = blockIdx.x * 64;
    const float* X = x + (size_t)b * DIM * LSEQ;
    const int tid = threadIdx.x;

    for (int dc = 0; dc < DIM; dc += 32) {
#pragma unroll
        for (int p = 0; p < 8; p++) {
            int d = p * 4 + (tid >> 6);
            int l = tid & 63;
            sm[d][l] = X[(size_t)(dc + d) * LSEQ + l0 + l];
        }
        __syncthreads();

        int l  = tid >> 2;
        int dq = (tid & 3) * 8;
        uint32_t hp[4];
#pragma unroll
        for (int j = 0; j < 4; j++) {
            __half h0 = __float2half(sm[dq + 2 * j][l]);
            __half h1 = __float2half(sm[dq + 2 * j + 1][l]);
            hp[j] = ((uint32_t)__half_as_ushort(h1) << 16) | __half_as_ushort(h0);
        }
        *reinterpret_cast<uint4*>(&g_Xb[(size_t)(b * LSEQ + l0 + l) * 512 + dc + dq]) =
            make_uint4(hp[0], hp[1], hp[2], hp[3]);
        __syncthreads();
    }
}

// ---------------------------------------------------------------------------
// GEMM: C[1024 x 65536] = Wh[1024 x 512] @ Xh[512 x 65536], pure fp16 K=512.
// Block 256x128, BK=64, 8 warps (4m x 2n), warp tile 64x64.
// cp.async 3-stage (48KB/stage), ldmatrix.x4, XOR-swizzled smem,
// fused (a,b) epilogue writing half2. Grid (4 m, 512 n) -- m fastest.
// ---------------------------------------------------------------------------
#define STAGE_BYTES 49152     // A 32KB + B 16KB
#define NK 8                  // 8 x BK64 = 512

__global__ __launch_bounds__(256, 1)
void gemm_hmma3(const float* __restrict__ bf_, const float* __restrict__ bb_)
{
    extern __shared__ __align__(128) unsigned char smraw[];
    const int tid  = threadIdx.x;
    const int lane = tid & 31;
    const int wid  = tid >> 5;
    const int mw   = wid & 3;          // 0..3  (64-row m slice)
    const int nw   = wid >> 2;         // 0..1  (64-col n slice)
    const int mbase = blockIdx.x * 256;
    const int nbase = blockIdx.y * 128;
    const uint32_t smb = smem_u32(smraw);

    float acc[4][8][4];
#pragma unroll
    for (int i = 0; i < 4; i++)
#pragma unroll
        for (int j = 0; j < 8; j++)
#pragma unroll
            for (int c = 0; c < 4; c++) acc[i][j][c] = 0.f;

    auto issue = [&](int i) {
        int k0 = i * 64;
        int buf = i % 3;
        uint32_t sA = smb + buf * STAGE_BYTES;
        uint32_t sB = sA + 32768;
        // A: 256 rows x 8 x 16B ; thread -> row tid, all 8 col-chunks
        {
            int r = tid;
            const __half* gA = &g_Wc[(size_t)(mbase + r) * 512 + k0];
            uint32_t base = sA + r * 128;
            uint32_t sw = (uint32_t)(r & 7) << 4;
#pragma unroll
            for (int c = 0; c < 8; c++) {
                uint32_t dA = base + (((uint32_t)(c << 4)) ^ sw);
                asm volatile("cp.async.cg.shared.global [%0], [%1], 16;"
                             :: "r"(dA), "l"(gA + c * 8));
            }
        }
        // B: 128 rows x 8 x 16B = 1024 chunks; 4 per thread
#pragma unroll
        for (int j = 0; j < 4; j++) {
            int q = tid * 4 + j;
            int r = q >> 3, c = q & 7;
            const void* gB = &g_Xb[(size_t)(nbase + r) * 512 + k0 + c * 8];
            uint32_t dB = sB + r * 128 + ((uint32_t)(c ^ (r & 7)) << 4);
            asm volatile("cp.async.cg.shared.global [%0], [%1], 16;"
                         :: "r"(dB), "l"(gB));
        }
        asm volatile("cp.async.commit_group;");
    };

    issue(0); issue(1); issue(2);

    const int rla = mw * 64 + (lane & 15);   // A smem row (within 256)
    const int rlb = nw * 64 + (lane & 15);   // B smem row (within 128)
    const int hi  = lane >> 4;               // chunk half selector

    for (int i = 0; i < NK; i++) {
        asm volatile("cp.async.wait_group 2;");
        __syncthreads();
        int buf = i % 3;
        uint32_t sA = smb + buf * STAGE_BYTES;
        uint32_t sB = sA + 32768;
#pragma unroll
        for (int ks = 0; ks < 4; ks++) {
            uint32_t af[4][4], bfr[4][4];
            uint32_t cxa = (uint32_t)((ks * 2 + hi) ^ (rla & 7)) << 4;
            uint32_t cxb = (uint32_t)((ks * 2 + hi) ^ (rlb & 7)) << 4;
#pragma unroll
            for (int mt = 0; mt < 4; mt++)
                ldsm4(af[mt], sA + (uint32_t)(rla + mt * 16) * 128 + cxa);
#pragma unroll
            for (int n2 = 0; n2 < 4; n2++)
                ldsm4(bfr[n2], sB + (uint32_t)(rlb + n2 * 16) * 128 + cxb);
#pragma unroll
            for (int mt = 0; mt < 4; mt++)
#pragma unroll
                for (int n2 = 0; n2 < 4; n2++) {
                    mma16816(acc[mt][2 * n2],     af[mt], bfr[n2][0], bfr[n2][2]);
                    mma16816(acc[mt][2 * n2 + 1], af[mt], bfr[n2][1], bfr[n2][3]);
                }
        }
        __syncthreads();
        if (i + 3 < NK) issue(i + 3);
        else asm volatile("cp.async.commit_group;");
    }

    // ---- fused epilogue: bias + (a,b) + half2 store ----
    const int t4 = lane >> 2, tm = lane & 3;
    const int bt = nbase >> 13;
    const int l0 = nbase & 8191;
#pragma unroll
    for (int mt = 0; mt < 4; mt++) {
        int rh = mbase + mw * 64 + mt * 16 + t4;       // h row (rh&15 < 8)
        int ch = ((rh >> 4) << 3) + (rh & 7);          // channel 0..511
        float bh, bg;
        if (ch < 256) { bh = bf_[ch];       bg = bf_[256 + ch]; }
        else          { bh = bb_[ch - 256]; bg = bb_[ch]; }
        size_t rowoff = ((size_t)bt * 512 + ch) * LSEQ + l0 + nw * 64 + tm * 2;
#pragma unroll
        for (int nt = 0; nt < 8; nt++) {
            float h0 = acc[mt][nt][0] + bh, h1 = acc[mt][nt][1] + bh;
            float g0 = acc[mt][nt][2] + bg, g1 = acc[mt][nt][3] + bg;
            float a0, b0, a1, b1;
            ab_elem(h0, g0, a0, b0);
            ab_elem(h1, g1, a1, b1);
            __half2 p0 = __floats2half2_rn(a0, b0);
            __half2 p1 = __floats2half2_rn(a1, b1);
            *reinterpret_cast<uint2*>(&g_AB[rowoff + nt * 8]) =
                make_uint2(*reinterpret_cast<uint32_t*>(&p0),
                           *reinterpret_cast<uint32_t*>(&p1));
        }
    }
}

// ---------------------------------------------------------------------------
// Scan v4: register-direct, no smem staging. 512 threads/block, one row each.
// Thread t owns 16 consecutive elements (64B chunk -> coalesced at sector
// level). Warp-shuffle 2-level block scan. Direct float4 stores.
// ---------------------------------------------------------------------------
__global__ __launch_bounds__(512)
void mingru_scan4(float* __restrict__ out)
{
    __shared__ float wAs[16], wBs[16];

    const int row = blockIdx.x;                // 0..4095
    const int b   = row >> 9;
    const int ch  = row & 511;
    const int dir = ch >> 8;                   // 0 fore, 1 back

    const __half2* abr = g_AB + ((size_t)b * 512 + ch) * LSEQ;
    float* orow = out + ((size_t)b * 512 + ch) * LSEQ;

    const int tid  = threadIdx.x;
    const int lane = tid & 31;
    const int w    = tid >> 5;

    const int base = dir ? (LSEQ - tid * 16 - 16) : tid * 16;

    // load 16 half2 (64B) directly
    uint4 d[4];
    const uint4* src = reinterpret_cast<const uint4*>(abr + base);
#pragma unroll
    for (int j = 0; j < 4; j++) d[j] = src[j];

    // unpack in scan order (reversed for back direction)
    float a[16], bv[16];
    const __half2* hp = reinterpret_cast<const __half2*>(d);
#pragma unroll
    for (int j = 0; j < 16; j++) {
        int jj = dir ? (15 - j) : j;
        float2 f = __half22float2(hp[jj]);
        a[j]  = f.x;
        bv[j] = f.y;
    }

    // local chunk summary
    float A = 1.f, Bc = 0.f;
#pragma unroll
    for (int j = 0; j < 16; j++) {
        Bc = fmaf(a[j], Bc, bv[j]);
        A *= a[j];
    }

    // warp inclusive scan (composition)
    float Ai = A, Bi = Bc;
#pragma unroll
    for (int off = 1; off < 32; off <<= 1) {
        float pA = __shfl_up_sync(0xffffffffu, Ai, off);
        float pB = __shfl_up_sync(0xffffffffu, Bi, off);
        if (lane >= off) {
            Bi = fmaf(Ai, pB, Bi);
            Ai = pA * Ai;
        }
    }
    if (lane == 31) { wAs[w] = Ai; wBs[w] = Bi; }
    __syncthreads();

    // warp 0 scans the 16 warp totals
    if (w == 0 && lane < 16) {
        float tA = wAs[lane], tB = wBs[lane];
#pragma unroll
        for (int off = 1; off < 16; off <<= 1) {
            float pA = __shfl_up_sync(0x0000ffffu, tA, off);
            float pB = __shfl_up_sync(0x0000ffffu, tB, off);
            if (lane >= off) {
                tB = fmaf(tA, pB, tB);
                tA = pA * tA;
            }
        }
        wAs[lane] = tA; wBs[lane] = tB;
    }
    __syncthreads();

    // exclusive prefix for this thread:
    // laneExcl = inclusive shifted by 1; warpExcl = previous warp total
    float Ae = __shfl_up_sync(0xffffffffu, Ai, 1);
    float Be = __shfl_up_sync(0xffffffffu, Bi, 1);
    if (lane == 0) { Ae = 1.f; Be = 0.f; }
    float Bw = (w == 0) ? 0.f : wBs[w - 1];
    float h  = fmaf(Ae, Bw, Be);     // h before this chunk (h_init = 0)

    // apply and stage output in address order
    float hout[16];
#pragma unroll
    for (int j = 0; j < 16; j++) {
        h = fmaf(a[j], h, bv[j]);
        hout[dir ? (15 - j) : j] = h;
    }
    float4* dst = reinterpret_cast<float4*>(orow + base);
#pragma unroll
    for (int j = 0; j < 4; j++)
        dst[j] = make_float4(hout[4 * j], hout[4 * j + 1],
                             hout[4 * j + 2], hout[4 * j + 3]);
}

// ---------------------------------------------------------------------------
// Launch
// ---------------------------------------------------------------------------
extern "C" void kernel_launch(void* const* d_in, const int* in_sizes, int n_in,
                              void* d_out, int out_size)
{
    const float* x  = (const float*)d_in[0];
    const float* wf = (const float*)d_in[1];
    const float* bf = (const float*)d_in[2];
    const float* wb = (const float*)d_in[3];
    const float* bb = (const float*)d_in[4];
    float* out = (float*)d_out;

    cudaFuncSetAttribute(gemm_hmma3,
                         cudaFuncAttributeMaxDynamicSharedMemorySize,
                         3 * STAGE_BYTES);

    convert_w<<<512, 256>>>(wf, wb);
    convert_x<<<dim3(128, 8), 256>>>(x);

    gemm_hmma3<<<dim3(4, 512), 256, 3 * STAGE_BYTES>>>(bf, bb);

    mingru_scan4<<<4096, 512>>>(out);
}

// round 15
// speedup vs baseline: 1.2516x; 1.2516x over previous
#include <cuda_runtime.h>
#include <cuda_fp16.h>
#include <cstdint>

#define BATCH 8
#define DIM   512
#define LSEQ  8192

// ---------------- device scratch (static globals: allowed) ----------------
__device__ __half g_Wc[1024 * 512];                         //   1 MB
__device__ __half g_Xb[(size_t)65536 * 512];                //  64 MB [n=(b,l)][k]
__device__ __half2 g_AB[(size_t)BATCH * 512 * LSEQ];        // 128 MB  (a,b) pairs

__device__ __forceinline__ uint32_t smem_u32(const void* p) {
    uint32_t a;
    asm("{ .reg .u64 t; cvta.to.shared.u64 t, %1; cvt.u32.u64 %0, t; }"
        : "=r"(a) : "l"(p));
    return a;
}
__device__ __forceinline__ void ldsm4(uint32_t* d, uint32_t addr) {
    asm volatile("ldmatrix.sync.aligned.m8n8.x4.shared.b16 {%0,%1,%2,%3}, [%4];"
                 : "=r"(d[0]), "=r"(d[1]), "=r"(d[2]), "=r"(d[3]) : "r"(addr));
}
__device__ __forceinline__ void mma16816(float* c, const uint32_t* a,
                                         uint32_t b0, uint32_t b1) {
    asm volatile(
        "mma.sync.aligned.m16n8k16.row.col.f32.f16.f16.f32 "
        "{%0,%1,%2,%3}, {%4,%5,%6,%7}, {%8,%9}, {%0,%1,%2,%3};"
        : "+f"(c[0]), "+f"(c[1]), "+f"(c[2]), "+f"(c[3])
        : "r"(a[0]), "r"(a[1]), "r"(a[2]), "r"(a[3]), "r"(b0), "r"(b1));
}

// pointwise: a = sigmoid(-g), b = sigmoid(g) * (h>=0 ? 1+h : exp(h))
__device__ __forceinline__ void ab_elem(float h, float g, float& a, float& b) {
    float em = __expf(-g);
    float z  = __fdividef(1.f, 1.f + em);   // sigmoid(g); em=inf -> z=0
    a = 1.f - z;
    float gv = (h >= 0.f) ? (1.f + h) : __expf(h);
    b = z * gv;
}

// ---------------------------------------------------------------------------
// W converter: fragment-friendly row reorder, fp16 quantize.
// ---------------------------------------------------------------------------
__global__ __launch_bounds__(256)
void convert_w(const float* __restrict__ wf, const float* __restrict__ wb)
{
    int idx = blockIdx.x * 256 + threadIdx.x;        // 0..131071
    int r   = idx >> 7;                              // 0..1023
    int dq  = (idx & 127) * 4;                       // 0..508
    int g   = r >> 4, i = r & 15;
    int ch  = (g << 3) + (i & 7);                    // 0..511
    int gate = i >> 3;
    const float* src = (ch < 256)
        ? wf + (size_t)(gate * 256 + ch) * DIM + dq
        : wb + (size_t)(gate * 256 + ch - 256) * DIM + dq;
    float4 v = *reinterpret_cast<const float4*>(src);
    float vv[4] = {v.x, v.y, v.z, v.w};
#pragma unroll
    for (int j = 0; j < 4; j++)
        g_Wc[(size_t)r * 512 + dq + j] = __float2half(vv[j]);
}

// ---------------------------------------------------------------------------
// X converter: x[b][d][l] -> g_Xb[(b*8192+l)][d] fp16 via smem transpose.
// ---------------------------------------------------------------------------
__global__ __launch_bounds__(256)
void convert_x(const float* __restrict__ x)
{
    __shared__ float sm[32][65];
    const int b  = blockIdx.y;
    const int l0 = blockIdx.x * 64;
    const float* X = x + (size_t)b * DIM * LSEQ;
    const int tid = threadIdx.x;

    for (int dc = 0; dc < DIM; dc += 32) {
#pragma unroll
        for (int p = 0; p < 8; p++) {
            int d = p * 4 + (tid >> 6);
            int l = tid & 63;
            sm[d][l] = X[(size_t)(dc + d) * LSEQ + l0 + l];
        }
        __syncthreads();

        int l  = tid >> 2;
        int dq = (tid & 3) * 8;
        uint32_t hp[4];
#pragma unroll
        for (int j = 0; j < 4; j++) {
            __half h0 = __float2half(sm[dq + 2 * j][l]);
            __half h1 = __float2half(sm[dq + 2 * j + 1][l]);
            hp[j] = ((uint32_t)__half_as_ushort(h1) << 16) | __half_as_ushort(h0);
        }
        *reinterpret_cast<uint4*>(&g_Xb[(size_t)(b * LSEQ + l0 + l) * 512 + dc + dq]) =
            make_uint4(hp[0], hp[1], hp[2], hp[3]);
        __syncthreads();
    }
}

// ---------------------------------------------------------------------------
// GEMM (R13 config): C[1024 x 65536] = Wh[1024 x 512] @ Xh[512 x 65536], fp16.
// Block 128x128, BK=64, 8 warps (2m x 4n), warp tile 64x32, 2 CTAs/SM.
// cp.async 3-stage, ldmatrix.x4, XOR-swizzled smem, fused (a,b) epilogue.
// Grid (8 m, 512 n) -- m fastest so B tiles are L2-shared.
// ---------------------------------------------------------------------------
#define STAGE_BYTES 32768     // A 16KB + B 16KB
#define NK 8                  // 8 x BK64 = 512

__global__ __launch_bounds__(256, 2)
void gemm_hmma2(const float* __restrict__ bf_, const float* __restrict__ bb_)
{
    extern __shared__ __align__(128) unsigned char smraw[];
    const int tid  = threadIdx.x;
    const int lane = tid & 31;
    const int wid  = tid >> 5;
    const int mw   = wid & 1;
    const int nw   = wid >> 1;
    const int mbase = blockIdx.x * 128;
    const int nbase = blockIdx.y * 128;
    const uint32_t smb = smem_u32(smraw);

    float acc[4][4][4];
#pragma unroll
    for (int i = 0; i < 4; i++)
#pragma unroll
        for (int j = 0; j < 4; j++)
#pragma unroll
            for (int c = 0; c < 4; c++) acc[i][j][c] = 0.f;

    auto issue = [&](int i) {
        int k0 = i * 64;
        int buf = i % 3;
        uint32_t sA = smb + buf * STAGE_BYTES;
        uint32_t sB = sA + 16384;
#pragma unroll
        for (int j = 0; j < 4; j++) {
            int q = tid * 4 + j;          // 0..1023
            int r = q >> 3, c = q & 7;
            const void* gA = &g_Wc[(size_t)(mbase + r) * 512 + k0 + c * 8];
            uint32_t dA = sA + r * 128 + ((uint32_t)(c ^ (r & 7)) << 4);
            asm volatile("cp.async.cg.shared.global [%0], [%1], 16;"
                         :: "r"(dA), "l"(gA));
            const void* gB = &g_Xb[(size_t)(nbase + r) * 512 + k0 + c * 8];
            uint32_t dB = sB + r * 128 + ((uint32_t)(c ^ (r & 7)) << 4);
            asm volatile("cp.async.cg.shared.global [%0], [%1], 16;"
                         :: "r"(dB), "l"(gB));
        }
        asm volatile("cp.async.commit_group;");
    };

    issue(0); issue(1); issue(2);

    const int rla = mw * 64 + (lane & 15);   // A smem row (within 128)
    const int rlb = nw * 32 + (lane & 15);   // B smem row
    const int hi  = lane >> 4;               // chunk half selector

    for (int i = 0; i < NK; i++) {
        asm volatile("cp.async.wait_group 2;");
        __syncthreads();
        int buf = i % 3;
        uint32_t sA = smb + buf * STAGE_BYTES;
        uint32_t sB = sA + 16384;
#pragma unroll
        for (int ks = 0; ks < 4; ks++) {
            uint32_t af[4][4], bfr[2][4];
            uint32_t cxa = (uint32_t)((ks * 2 + hi) ^ (rla & 7)) << 4;
            uint32_t cxb = (uint32_t)((ks * 2 + hi) ^ (rlb & 7)) << 4;
#pragma unroll
            for (int mt = 0; mt < 4; mt++)
                ldsm4(af[mt], sA + (uint32_t)(rla + mt * 16) * 128 + cxa);
#pragma unroll
            for (int n2 = 0; n2 < 2; n2++)
                ldsm4(bfr[n2], sB + (uint32_t)(rlb + n2 * 16) * 128 + cxb);
#pragma unroll
            for (int mt = 0; mt < 4; mt++) {
                mma16816(acc[mt][0], af[mt], bfr[0][0], bfr[0][2]);
                mma16816(acc[mt][1], af[mt], bfr[0][1], bfr[0][3]);
                mma16816(acc[mt][2], af[mt], bfr[1][0], bfr[1][2]);
                mma16816(acc[mt][3], af[mt], bfr[1][1], bfr[1][3]);
            }
        }
        __syncthreads();
        if (i + 3 < NK) issue(i + 3);
        else asm volatile("cp.async.commit_group;");
    }

    // ---- fused epilogue: bias + (a,b) + half2 store ----
    const int t4 = lane >> 2, tm = lane & 3;
    const int bt = nbase >> 13;
    const int l0 = nbase & 8191;
#pragma unroll
    for (int mt = 0; mt < 4; mt++) {
        int rh = mbase + mw * 64 + mt * 16 + t4;       // h row (rh&15 < 8)
        int ch = ((rh >> 4) << 3) + (rh & 7);          // channel 0..511
        float bh, bg;
        if (ch < 256) { bh = bf_[ch];       bg = bf_[256 + ch]; }
        else          { bh = bb_[ch - 256]; bg = bb_[ch]; }
        size_t rowoff = ((size_t)bt * 512 + ch) * LSEQ + l0 + nw * 32 + tm * 2;
#pragma unroll
        for (int nt = 0; nt < 4; nt++) {
            float h0 = acc[mt][nt][0] + bh, h1 = acc[mt][nt][1] + bh;
            float g0 = acc[mt][nt][2] + bg, g1 = acc[mt][nt][3] + bg;
            float a0, b0, a1, b1;
            ab_elem(h0, g0, a0, b0);
            ab_elem(h1, g1, a1, b1);
            __half2 p0 = __floats2half2_rn(a0, b0);
            __half2 p1 = __floats2half2_rn(a1, b1);
            *reinterpret_cast<uint2*>(&g_AB[rowoff + nt * 8]) =
                make_uint2(*reinterpret_cast<uint32_t*>(&p0),
                           *reinterpret_cast<uint32_t*>(&p1));
        }
    }
}

// ---------------------------------------------------------------------------
// Scan v4 (R14): register-direct, warp-shuffle 2-level block scan.
// 512 threads/block, one row per block, 16 elems/thread, float4 I/O.
// ---------------------------------------------------------------------------
__global__ __launch_bounds__(512)
void mingru_scan4(float* __restrict__ out)
{
    __shared__ float wAs[16], wBs[16];

    const int row = blockIdx.x;                // 0..4095
    const int b   = row >> 9;
    const int ch  = row & 511;
    const int dir = ch >> 8;                   // 0 fore, 1 back

    const __half2* abr = g_AB + ((size_t)b * 512 + ch) * LSEQ;
    float* orow = out + ((size_t)b * 512 + ch) * LSEQ;

    const int tid  = threadIdx.x;
    const int lane = tid & 31;
    const int w    = tid >> 5;

    const int base = dir ? (LSEQ - tid * 16 - 16) : tid * 16;

    uint4 d[4];
    const uint4* src = reinterpret_cast<const uint4*>(abr + base);
#pragma unroll
    for (int j = 0; j < 4; j++) d[j] = src[j];

    float a[16], bv[16];
    const __half2* hp = reinterpret_cast<const __half2*>(d);
#pragma unroll
    for (int j = 0; j < 16; j++) {
        int jj = dir ? (15 - j) : j;
        float2 f = __half22float2(hp[jj]);
        a[j]  = f.x;
        bv[j] = f.y;
    }

    float A = 1.f, Bc = 0.f;
#pragma unroll
    for (int j = 0; j < 16; j++) {
        Bc = fmaf(a[j], Bc, bv[j]);
        A *= a[j];
    }

    float Ai = A, Bi = Bc;
#pragma unroll
    for (int off = 1; off < 32; off <<= 1) {
        float pA = __shfl_up_sync(0xffffffffu, Ai, off);
        float pB = __shfl_up_sync(0xffffffffu, Bi, off);
        if (lane >= off) {
            Bi = fmaf(Ai, pB, Bi);
            Ai = pA * Ai;
        }
    }
    if (lane == 31) { wAs[w] = Ai; wBs[w] = Bi; }
    __syncthreads();

    if (w == 0 && lane < 16) {
        float tA = wAs[lane], tB = wBs[lane];
#pragma unroll
        for (int off = 1; off < 16; off <<= 1) {
            float pA = __shfl_up_sync(0x0000ffffu, tA, off);
            float pB = __shfl_up_sync(0x0000ffffu, tB, off);
            if (lane >= off) {
                tB = fmaf(tA, pB, tB);
                tA = pA * tA;
            }
        }
        wAs[lane] = tA; wBs[lane] = tB;
    }
    __syncthreads();

    float Ae = __shfl_up_sync(0xffffffffu, Ai, 1);
    float Be = __shfl_up_sync(0xffffffffu, Bi, 1);
    if (lane == 0) { Ae = 1.f; Be = 0.f; }
    float Bw = (w == 0) ? 0.f : wBs[w - 1];
    float h  = fmaf(Ae, Bw, Be);     // h before this chunk (h_init = 0)

    float hout[16];
#pragma unroll
    for (int j = 0; j < 16; j++) {
        h = fmaf(a[j], h, bv[j]);
        hout[dir ? (15 - j) : j] = h;
    }
    float4* dst = reinterpret_cast<float4*>(orow + base);
#pragma unroll
    for (int j = 0; j < 4; j++)
        dst[j] = make_float4(hout[4 * j], hout[4 * j + 1],
                             hout[4 * j + 2], hout[4 * j + 3]);
}

// ---------------------------------------------------------------------------
// Launch
// ---------------------------------------------------------------------------
extern "C" void kernel_launch(void* const* d_in, const int* in_sizes, int n_in,
                              void* d_out, int out_size)
{
    const float* x  = (const float*)d_in[0];
    const float* wf = (const float*)d_in[1];
    const float* bf = (const float*)d_in[2];
    const float* wb = (const float*)d_in[3];
    const float* bb = (const float*)d_in[4];
    float* out = (float*)d_out;

    cudaFuncSetAttribute(gemm_hmma2,
                         cudaFuncAttributeMaxDynamicSharedMemorySize,
                         3 * STAGE_BYTES);

    convert_w<<<512, 256>>>(wf, wb);
    convert_x<<<dim3(128, 8), 256>>>(x);

    gemm_hmma2<<<dim3(8, 512), 256, 3 * STAGE_BYTES>>>(bf, bb);

    mingru_scan4<<<4096, 512>>>(out);
}